// round 10
// baseline (speedup 1.0000x reference)
#include <cuda_runtime.h>
#include <cuda_bf16.h>

// CompositeValueNoise, spatially-binned v8.
// vs R9: main kernel restructured for occupancy — one level's 8-load batch at
// a time (32 live buffer regs instead of 64) targeting <=64 regs/thread so a
// full 32-warp complement hides L2 latency; level cells/fractions derived
// from a single res-128 computation. Sort pipeline unchanged.

#define N_FIELDS 4
#define MAXN 2000000
#define BBITS 6
#define BDIM (1 << BBITS)            // 64
#define NBUCK (BDIM * BDIM * BDIM)   // 262144
#define SCAN_BLKS (NBUCK / 1024)     // 256

__device__ int    g_hist[NBUCK];
__device__ int    g_counter;
__device__ float4 g_sorted[MAXN];

__device__ __forceinline__ int cell_key(float px, float py, float pz) {
    int ci = min(max((int)(px * (float)BDIM), 0), BDIM - 1);
    int cj = min(max((int)(py * (float)BDIM), 0), BDIM - 1);
    int ck = min(max((int)(pz * (float)BDIM), 0), BDIM - 1);
    return (ci << (2 * BBITS)) | (cj << BBITS) | ck;   // k innermost
}

__global__ void zero_hist_kernel() {
    int i = blockIdx.x * blockDim.x + threadIdx.x;
    if (i < NBUCK / 4)
        reinterpret_cast<int4*>(g_hist)[i] = make_int4(0, 0, 0, 0);
    if (i == 0) g_counter = 0;
}

__global__ void hist_kernel(const float* __restrict__ x, int n) {
    int t = blockIdx.x * blockDim.x + threadIdx.x;
    int p0 = t * 4;
    if (p0 >= n) return;
    if (p0 + 4 <= n) {
        const float4* xv = reinterpret_cast<const float4*>(x) + 3 * (size_t)t;
        float4 a = __ldg(xv + 0), b = __ldg(xv + 1), c = __ldg(xv + 2);
        atomicAdd(&g_hist[cell_key(a.x, a.y, a.z)], 1);
        atomicAdd(&g_hist[cell_key(a.w, b.x, b.y)], 1);
        atomicAdd(&g_hist[cell_key(b.z, b.w, c.x)], 1);
        atomicAdd(&g_hist[cell_key(c.y, c.z, c.w)], 1);
    } else {
        for (int p = p0; p < n; ++p)
            atomicAdd(&g_hist[cell_key(x[3*p], x[3*p+1], x[3*p+2])], 1);
    }
}

// Coalesced block scan of 1024 ints; block takes its global segment base via
// one early atomicAdd on g_counter, folded into the stored prefixes, so
// g_hist ends holding ABSOLUTE exclusive bucket bases. Segment order is
// run-arbitrary; each point's slot and value are unchanged -> deterministic.
__global__ void scan1_kernel() {
    __shared__ int warp_sums[8];
    __shared__ int s_base;
    int b = blockIdx.x, t = threadIdx.x;
    int lane = t & 31, wid = t >> 5;
    int base = b * 1024 + t * 4;

    int4 v = *reinterpret_cast<int4*>(&g_hist[base]);
    int tot = v.x + v.y + v.z + v.w;

    int inc = tot;
    #pragma unroll
    for (int o = 1; o < 32; o <<= 1) {
        int u = __shfl_up_sync(0xffffffffu, inc, o);
        if (lane >= o) inc += u;
    }
    if (lane == 31) warp_sums[wid] = inc;
    __syncthreads();
    if (wid == 0 && lane < 8) {
        int w = warp_sums[lane];
        #pragma unroll
        for (int o = 1; o < 8; o <<= 1) {
            int u = __shfl_up_sync(0xffu, w, o);
            if (lane >= o) w += u;
        }
        warp_sums[lane] = w;
        if (lane == 7) s_base = atomicAdd(&g_counter, w);  // w == block total
    }
    __syncthreads();
    int excl = s_base + (wid ? warp_sums[wid - 1] : 0) + inc - tot;

    int4 r;
    r.x = excl;
    r.y = excl + v.x;
    r.z = excl + v.x + v.y;
    r.w = excl + v.x + v.y + v.z;
    *reinterpret_cast<int4*>(&g_hist[base]) = r;
}

__device__ __forceinline__ void scatter_one(float px, float py, float pz, int i) {
    int pos = atomicAdd(&g_hist[cell_key(px, py, pz)], 1);
    g_sorted[pos] = make_float4(px, py, pz, __int_as_float(i));
}

__global__ void scatter_kernel(const float* __restrict__ x, int n) {
    int t = blockIdx.x * blockDim.x + threadIdx.x;
    int p0 = t * 4;
    if (p0 >= n) return;
    if (p0 + 4 <= n) {
        const float4* xv = reinterpret_cast<const float4*>(x) + 3 * (size_t)t;
        float4 a = __ldg(xv + 0), b = __ldg(xv + 1), c = __ldg(xv + 2);
        scatter_one(a.x, a.y, a.z, p0 + 0);
        scatter_one(a.w, b.x, b.y, p0 + 1);
        scatter_one(b.z, b.w, c.x, p0 + 2);
        scatter_one(c.y, c.z, c.w, p0 + 3);
    } else {
        for (int p = p0; p < n; ++p)
            scatter_one(x[3*p], x[3*p+1], x[3*p+2], p);
    }
}

__device__ __forceinline__ float4 ld4(const float* __restrict__ p) {
    return __ldg(reinterpret_cast<const float4*>(p));
}

__device__ __forceinline__ float4 lerp4(float4 a, float4 b, float w) {
    float4 r;
    r.x = fmaf(w, b.x - a.x, a.x);
    r.y = fmaf(w, b.y - a.y, a.y);
    r.z = fmaf(w, b.z - a.z, a.z);
    r.w = fmaf(w, b.w - a.w, a.w);
    return r;
}

// One noise level. Cells/fractions derived from the res-128 values:
// for shift s (res = 128 >> s): cell = c128 >> s, frac = (xs128 - cell*2^s)/2^s
// — exact in fp32 since only powers of two are involved.
template <int RES>
__device__ __forceinline__ float4 level_noise(
    const float* __restrict__ V,
    float xs128, float ys128, float zs128,
    int c128x, int c128y, int c128z)
{
    constexpr int SHIFT = (RES == 128) ? 0 : (RES == 64) ? 1 : (RES == 32) ? 2 : 3;
    constexpr float INV = 1.0f / (float)(1 << SHIFT);

    int i0 = c128x >> SHIFT, j0 = c128y >> SHIFT, k0 = c128z >> SHIFT;
    float tx = (xs128 - (float)(i0 << SHIFT)) * INV;
    float ty = (ys128 - (float)(j0 << SHIFT)) * INV;
    float tz = (zs128 - (float)(k0 << SHIFT)) * INV;

    float wx = (3.0f - 2.0f * tx) * tx * tx;
    float wy = (3.0f - 2.0f * ty) * ty * ty;
    float wz = (3.0f - 2.0f * tz) * tz * tz;

    constexpr int S1 = (RES + 1) * N_FIELDS;
    constexpr int S0 = (RES + 1) * S1;

    const float* base = V + (size_t)i0 * S0 + (size_t)j0 * S1 + (size_t)k0 * N_FIELDS;

    float4 v0 = ld4(base);
    float4 v1 = ld4(base + N_FIELDS);
    float4 v2 = ld4(base + S1);
    float4 v3 = ld4(base + S1 + N_FIELDS);
    float4 v4 = ld4(base + S0);
    float4 v5 = ld4(base + S0 + N_FIELDS);
    float4 v6 = ld4(base + S0 + S1);
    float4 v7 = ld4(base + S0 + S1 + N_FIELDS);

    float4 a00 = lerp4(v0, v4, wx);
    float4 a01 = lerp4(v1, v5, wx);
    float4 a10 = lerp4(v2, v6, wx);
    float4 a11 = lerp4(v3, v7, wx);
    float4 b0 = lerp4(a00, a10, wy);
    float4 b1 = lerp4(a01, a11, wy);
    return lerp4(b0, b1, wz);
}

__global__ void __launch_bounds__(256) composite_value_noise_kernel(
    const float* __restrict__ V16,
    const float* __restrict__ V32,
    const float* __restrict__ V64,
    const float* __restrict__ V128,
    float* __restrict__ out,
    int n)
{
    int p = blockIdx.x * blockDim.x + threadIdx.x;
    if (p >= n) return;

    float4 pt = g_sorted[p];
    const int idx = __float_as_int(pt.w);

    // res-128 coordinates; all levels derive from these (powers of two).
    float xs = pt.x * 128.0f, ys = pt.y * 128.0f, zs = pt.z * 128.0f;
    int cx = (int)xs, cy = (int)ys, cz = (int)zs;   // x in [0,1): floor == trunc

    float4 n0 = level_noise<16>(V16, xs, ys, zs, cx, cy, cz);
    float4 n1 = level_noise<32>(V32, xs, ys, zs, cx, cy, cz);
    float4 n2 = level_noise<64>(V64, xs, ys, zs, cx, cy, cz);
    float4 n3 = level_noise<128>(V128, xs, ys, zs, cx, cy, cz);

    float4 acc;
    acc.x = fmaf(0.125f, n3.x, fmaf(0.25f, n2.x, fmaf(0.5f, n1.x, n0.x)));
    acc.y = fmaf(0.125f, n3.y, fmaf(0.25f, n2.y, fmaf(0.5f, n1.y, n0.y)));
    acc.z = fmaf(0.125f, n3.z, fmaf(0.25f, n2.z, fmaf(0.5f, n1.z, n0.z)));
    acc.w = fmaf(0.125f, n3.w, fmaf(0.25f, n2.w, fmaf(0.5f, n1.w, n0.w)));

    reinterpret_cast<float4*>(out)[idx] = acc;
}

extern "C" void kernel_launch(void* const* d_in, const int* in_sizes, int n_in,
                              void* d_out, int out_size) {
    const float* x    = (const float*)d_in[0];
    const float* V16  = (const float*)d_in[1];
    const float* V32  = (const float*)d_in[2];
    const float* V64  = (const float*)d_in[3];
    const float* V128 = (const float*)d_in[4];
    float* out = (float*)d_out;

    int n = in_sizes[0] / 3;
    const int T = 256;
    int nquads = (n + 3) / 4;

    zero_hist_kernel<<<(NBUCK / 4 + T - 1) / T, T>>>();
    hist_kernel<<<(nquads + T - 1) / T, T>>>(x, n);
    scan1_kernel<<<SCAN_BLKS, 256>>>();
    scatter_kernel<<<(nquads + T - 1) / T, T>>>(x, n);

    int blocks = (n + T - 1) / T;
    composite_value_noise_kernel<<<blocks, T>>>(V16, V32, V64, V128, out, n);
}